// round 1
// baseline (speedup 1.0000x reference)
#include <cuda_runtime.h>

// Problem constants
#define GH 64
#define GW 64
#define NOBJ 16
#define FEAT 256
#define BATCH 4
#define DECAY 0.95f

// rows = B*GH*GW*NOBJ = 262144; each output row = FEAT+2 = 258 floats (1032 B)
#define NROWS (BATCH * GH * GW * NOBJ)
#define ROW_OUT (FEAT + 2)

// 256 threads/block, 2 rows per block: threads [0,128) -> row0, [128,256) -> row1.
// Each thread moves one float2 of the 256-float feature section; lane 0 of each
// row-group also writes the (conf*DECAY, temporal) trailing float2.
__global__ __launch_bounds__(256, 8)
void smg_kernel(const float* __restrict__ grid_state,
                const float* __restrict__ grid_conf,
                const float* __restrict__ grid_temp,
                const float* __restrict__ obj_feat,
                const float* __restrict__ positions,
                const float* __restrict__ occl,
                float* __restrict__ out)
{
    const int local_row = threadIdx.x >> 7;          // 0 or 1
    const int t         = threadIdx.x & 127;         // float2 index within row
    const int row       = blockIdx.x * 2 + local_row;

    // Decompose row -> (b, gh, gw, obj)
    const int obj  = row & (NOBJ - 1);
    const int cell = row >> 4;
    const int gw   = cell & (GW - 1);
    const int gh   = (cell >> 6) & (GH - 1);
    const int b    = cell >> 12;
    const int bo   = b * NOBJ + obj;

    // position_to_grid for this (b, obj): scale, clamp (float), truncate.
    // Warp-uniform broadcast loads (tiny table, L1-resident).
    const float px = positions[bo * 2 + 0];
    const float py = positions[bo * 2 + 1];
    const int gw_t = (int)fminf(fmaxf(px * (float)(GW - 1), 0.0f), 63.0f);
    const int gh_t = (int)fminf(fmaxf(py * (float)(GH - 1), 0.0f), 63.0f);
    const bool upd = (gw_t == gw) && (gh_t == gh);

    // ---- feature section: one float2 per thread ----
    const float2* src = (const float2*)(grid_state + (size_t)row * FEAT);
    float2 v = src[t];

    if (upd) {
        const bool visible = occl[bo] < 0.5f;
        const float a  = visible ? 0.8f : 0.3f;
        const float ia = 1.0f - a;
        const float2 o2 = ((const float2*)(obj_feat + (size_t)bo * FEAT))[t];
        v.x = a * o2.x + ia * v.x;
        v.y = a * o2.y + ia * v.y;
    }

    float* orow = out + (size_t)row * ROW_OUT;       // 8B-aligned (1032 % 8 == 0)
    *(float2*)(orow + 2 * t) = v;

    // ---- conf + temporal pair (lane 0 of each row-group) ----
    if (t == 0) {
        float c  = grid_conf[row];
        float tm = grid_temp[row];
        if (upd) {
            const bool visible = occl[bo] < 0.5f;
            c  = visible ? fminf(1.0f, c * 0.9f + 0.5f) : c * DECAY;
            tm += visible ? 1.0f : 0.5f;
        }
        float2 ct = make_float2(c * DECAY, tm);
        *(float2*)(orow + FEAT) = ct;                // byte off row*1032+1024, 8B-aligned
    }
}

extern "C" void kernel_launch(void* const* d_in, const int* in_sizes, int n_in,
                              void* d_out, int out_size)
{
    const float* grid_state = (const float*)d_in[0];
    const float* grid_conf  = (const float*)d_in[1];
    const float* grid_temp  = (const float*)d_in[2];
    const float* obj_feat   = (const float*)d_in[3];
    const float* positions  = (const float*)d_in[4];
    const float* occl       = (const float*)d_in[5];
    float* out = (float*)d_out;

    smg_kernel<<<NROWS / 2, 256>>>(grid_state, grid_conf, grid_temp,
                                   obj_feat, positions, occl, out);
}

// round 3
// speedup vs baseline: 1.6981x; 1.6981x over previous
#include <cuda_runtime.h>

#define GH 64
#define GW 64
#define NOBJ 16
#define FEAT 256
#define BATCH 4
#define DECAY 0.95f

#define NROWS (BATCH * GH * GW * NOBJ)   // 262144
#define ROW_OUT (FEAT + 2)               // 258 floats = 1032 B
#define RPB NOBJ                         // one cell (16 object-rows) per block

// One block per grid cell (b,gh,gw).
// Threads 0..15: compute per-object alpha -> smem, and write the
//                (conf*DECAY, temporal) trailing float2 straight to gmem.
// All 256 threads: stream 16x256 features, LDG.128 in, blend, 2x STG.64 out
//                  (output rows are 1032B-pitched -> 8B alignment guaranteed).
__global__ __launch_bounds__(256, 8)
void smg_kernel(const float* __restrict__ grid_state,
                const float* __restrict__ grid_conf,
                const float* __restrict__ grid_temp,
                const float* __restrict__ obj_feat,
                const float* __restrict__ positions,
                const float* __restrict__ occl,
                float* __restrict__ out)
{
    __shared__ float s_alpha[NOBJ];

    const int tid  = threadIdx.x;
    const int cell = blockIdx.x;                 // 0 .. 16383
    const int gw   = cell & (GW - 1);
    const int gh   = (cell >> 6) & (GH - 1);
    const int b    = cell >> 12;
    const int row0 = cell * RPB;

    // ---- Phase 0: per-object scalars (threads 0..15) ----
    if (tid < NOBJ) {
        const int o   = tid;
        const int bo  = b * NOBJ + o;
        const int row = row0 + o;
        const float px = positions[bo * 2 + 0];
        const float py = positions[bo * 2 + 1];
        const int gwt = (int)fminf(fmaxf(px * (float)(GW - 1), 0.0f), 63.0f);
        const int ght = (int)fminf(fmaxf(py * (float)(GH - 1), 0.0f), 63.0f);
        const bool upd = (gwt == gw) && (ght == gh);
        const bool vis = occl[bo] < 0.5f;

        s_alpha[o] = upd ? (vis ? 0.8f : 0.3f) : 0.0f;

        float c  = grid_conf[row];
        float tm = grid_temp[row];
        if (upd) {
            c  = vis ? fminf(1.0f, c * 0.9f + 0.5f) : c * DECAY;
            tm += vis ? 1.0f : 0.5f;
        }
        // trailing pair: float offset row*258 + 256 (even -> 8B aligned)
        *(float2*)(out + (size_t)row * ROW_OUT + FEAT) = make_float2(c * DECAY, tm);
    }
    __syncthreads();

    // ---- Main: 1024 float4s of features per block (4 per thread) ----
    const float4* gs = (const float4*)grid_state + (size_t)row0 * (FEAT / 4);

    float4 v[4];
    #pragma unroll
    for (int j = 0; j < 4; j++)
        v[j] = gs[tid + 256 * j];                // front-batched LDG.128 (MLP=4)

    #pragma unroll
    for (int j = 0; j < 4; j++) {
        const int idx = tid + 256 * j;           // 0..1023
        const int rl  = idx >> 6;                // local row (object), warp-uniform
        const int q   = idx & 63;                // float4 index in row
        const float a = s_alpha[rl];
        if (a != 0.0f) {                         // warp-uniform, ~never taken
            const int bo = b * NOBJ + rl;
            const float4 o4 = ((const float4*)(obj_feat + (size_t)bo * FEAT))[q];
            const float ia = 1.0f - a;
            v[j].x = a * o4.x + ia * v[j].x;
            v[j].y = a * o4.y + ia * v[j].y;
            v[j].z = a * o4.z + ia * v[j].z;
            v[j].w = a * o4.w + ia * v[j].w;
        }
        float* orow = out + (size_t)(row0 + rl) * ROW_OUT + 4 * q; // 8B aligned
        *(float2*)(orow)     = make_float2(v[j].x, v[j].y);
        *(float2*)(orow + 2) = make_float2(v[j].z, v[j].w);
    }
}

extern "C" void kernel_launch(void* const* d_in, const int* in_sizes, int n_in,
                              void* d_out, int out_size)
{
    const float* grid_state = (const float*)d_in[0];
    const float* grid_conf  = (const float*)d_in[1];
    const float* grid_temp  = (const float*)d_in[2];
    const float* obj_feat   = (const float*)d_in[3];
    const float* positions  = (const float*)d_in[4];
    const float* occl       = (const float*)d_in[5];
    float* out = (float*)d_out;

    smg_kernel<<<NROWS / RPB, 256>>>(grid_state, grid_conf, grid_temp,
                                     obj_feat, positions, occl, out);
}